// round 13
// baseline (speedup 1.0000x reference)
#include <cuda_runtime.h>
#include <cstdint>

// Problem constants (fixed by setup_inputs)
#define B_  16
#define C_  3
#define H_  1024
#define W_  1024
#define CP_ 35                 // control-point grid 35x35
#define HW_ (H_ * W_)
#define STEP_ (2.0f / 1023.0f) // linspace(-1,1,1024) step

// ---------------------------------------------------------------------------
// Bilinear sample with border padding from the 35x35 control grid, replicating
// the reference's (buggy-looking but exact) double normalization:
//   cp = (g + 1) * 17           (in [0, 34])
//   ix = (cp + 1) * 0.5 * 34    (treated as if cp were in [-1,1])
// ---------------------------------------------------------------------------
__device__ __forceinline__ void sample_deformation(
    const float* __restrict__ cp, float gx, float gy,
    float& d0, float& d1)
{
    float cpx = gx * 17.0f + 17.0f;
    float cpy = gy * 17.0f + 17.0f;
    float ix = (cpx + 1.0f) * 0.5f * 34.0f;
    float iy = (cpy + 1.0f) * 0.5f * 34.0f;
    ix = fminf(fmaxf(ix, 0.0f), 34.0f);
    iy = fminf(fmaxf(iy, 0.0f), 34.0f);
    float ix0f = floorf(ix);
    float iy0f = floorf(iy);
    float wx = ix - ix0f;
    float wy = iy - iy0f;
    int ix0 = (int)ix0f;
    int iy0 = (int)iy0f;
    int ix1 = min(ix0 + 1, 34);
    int iy1 = min(iy0 + 1, 34);

    int o00 = iy0 * CP_ + ix0;
    int o01 = iy0 * CP_ + ix1;
    int o10 = iy1 * CP_ + ix0;
    int o11 = iy1 * CP_ + ix1;

    // channel 0
    {
        float v00 = __ldg(cp + o00);
        float v01 = __ldg(cp + o01);
        float v10 = __ldg(cp + o10);
        float v11 = __ldg(cp + o11);
        float top = v00 * (1.0f - wx) + v01 * wx;
        float bot = v10 * (1.0f - wx) + v11 * wx;
        d0 = top * (1.0f - wy) + bot * wy;
    }
    // channel 1
    {
        const float* cp1 = cp + CP_ * CP_;
        float v00 = __ldg(cp1 + o00);
        float v01 = __ldg(cp1 + o01);
        float v10 = __ldg(cp1 + o10);
        float v11 = __ldg(cp1 + o11);
        float top = v00 * (1.0f - wx) + v01 * wx;
        float bot = v10 * (1.0f - wx) + v11 * wx;
        d1 = top * (1.0f - wy) + bot * wy;
    }
}

// ---------------------------------------------------------------------------
// Kernel A: write the deformation field (2, 1024, 1024) to the output tail.
// ---------------------------------------------------------------------------
__global__ __launch_bounds__(256)
void def_field_kernel(const float* __restrict__ cp, float* __restrict__ def_out)
{
    int w = blockIdx.x * blockDim.x + threadIdx.x;
    int h = blockIdx.y;
    float gx = -1.0f + (float)w * STEP_;
    float gy = -1.0f + (float)h * STEP_;
    float d0, d1;
    sample_deformation(cp, gx, gy, d0, d1);
    int pix = h * W_ + w;
    def_out[pix]       = d0;
    def_out[HW_ + pix] = d1;
}

// ---------------------------------------------------------------------------
// Kernel B: fused deformation recompute + bilinear warp of x.
// Grid: (W/256, H, B). Each thread handles one pixel of one batch, 3 channels.
// ---------------------------------------------------------------------------
__global__ __launch_bounds__(256)
void warp_kernel(const float* __restrict__ x,
                 const float* __restrict__ cp,
                 float* __restrict__ out)
{
    int w = blockIdx.x * blockDim.x + threadIdx.x;
    int h = blockIdx.y;
    int b = blockIdx.z;

    float gx = -1.0f + (float)w * STEP_;
    float gy = -1.0f + (float)h * STEP_;

    float d0, d1;
    sample_deformation(cp, gx, gy, d0, d1);   // cp is 9.8KB -> L1 resident

    // samp = (gx + def[1], gy + def[0]), normalized in [-1,1] nominally
    float sx = gx + d1;
    float sy = gy + d0;

    float ix = (sx + 1.0f) * 0.5f * 1023.0f;
    float iy = (sy + 1.0f) * 0.5f * 1023.0f;
    ix = fminf(fmaxf(ix, 0.0f), 1023.0f);
    iy = fminf(fmaxf(iy, 0.0f), 1023.0f);
    float ix0f = floorf(ix);
    float iy0f = floorf(iy);
    float wx = ix - ix0f;
    float wy = iy - iy0f;
    int ix0 = (int)ix0f;
    int iy0 = (int)iy0f;
    int ix1 = min(ix0 + 1, W_ - 1);
    int iy1 = min(iy0 + 1, H_ - 1);

    float omwx = 1.0f - wx;
    float omwy = 1.0f - wy;

    const float* xb = x + (size_t)b * (C_ * HW_);
    size_t out_base = (size_t)b * (C_ * HW_) + (size_t)h * W_ + w;

    int r0 = iy0 * W_;
    int r1 = iy1 * W_;

#pragma unroll
    for (int c = 0; c < C_; c++) {
        const float* xc = xb + (size_t)c * HW_;
        float v00 = __ldg(xc + r0 + ix0);
        float v01 = __ldg(xc + r0 + ix1);
        float v10 = __ldg(xc + r1 + ix0);
        float v11 = __ldg(xc + r1 + ix1);
        float top = v00 * omwx + v01 * wx;
        float bot = v10 * omwx + v11 * wx;
        out[out_base + (size_t)c * HW_] = top * omwy + bot * wy;
    }
}

// ---------------------------------------------------------------------------
extern "C" void kernel_launch(void* const* d_in, const int* in_sizes, int n_in,
                              void* d_out, int out_size)
{
    const float* x  = (const float*)d_in[0];  // (16,3,1024,1024) f32
    const float* cp = (const float*)d_in[1];  // (1,2,35,35) f32
    float* out = (float*)d_out;               // transformed(192MB) ++ def(8MB)

    float* def_out = out + (size_t)B_ * C_ * HW_;

    dim3 blk(256, 1, 1);
    dim3 grdA(W_ / 256, H_, 1);
    def_field_kernel<<<grdA, blk>>>(cp, def_out);

    dim3 grdB(W_ / 256, H_, B_);
    warp_kernel<<<grdB, blk>>>(x, cp, out);
}

// round 14
// speedup vs baseline: 1.0907x; 1.0907x over previous
#include <cuda_runtime.h>
#include <cstdint>

// Problem constants (fixed by setup_inputs)
#define B_  16
#define C_  3
#define H_  1024
#define W_  1024
#define CP_ 35                 // control-point grid 35x35
#define HW_ (H_ * W_)
#define CHW_ (C_ * HW_)
#define STEP_ (2.0f / 1023.0f) // linspace(-1,1,1024) step

// ---------------------------------------------------------------------------
// Bilinear sample with border padding from the 35x35 control grid, replicating
// the reference's exact double normalization:
//   cp = (g + 1) * 17           (in [0, 34])
//   ix = (cp + 1) * 0.5 * 34    (treated as if cp were in [-1,1])
// ---------------------------------------------------------------------------
__device__ __forceinline__ void sample_deformation(
    const float* __restrict__ cp, float gx, float gy,
    float& d0, float& d1)
{
    float cpx = gx * 17.0f + 17.0f;
    float cpy = gy * 17.0f + 17.0f;
    float ix = (cpx + 1.0f) * 0.5f * 34.0f;
    float iy = (cpy + 1.0f) * 0.5f * 34.0f;
    ix = fminf(fmaxf(ix, 0.0f), 34.0f);
    iy = fminf(fmaxf(iy, 0.0f), 34.0f);
    float ix0f = floorf(ix);
    float iy0f = floorf(iy);
    float wx = ix - ix0f;
    float wy = iy - iy0f;
    int ix0 = (int)ix0f;
    int iy0 = (int)iy0f;
    int ix1 = min(ix0 + 1, 34);
    int iy1 = min(iy0 + 1, 34);

    int o00 = iy0 * CP_ + ix0;
    int o01 = iy0 * CP_ + ix1;
    int o10 = iy1 * CP_ + ix0;
    int o11 = iy1 * CP_ + ix1;

    // channel 0
    {
        float v00 = __ldg(cp + o00);
        float v01 = __ldg(cp + o01);
        float v10 = __ldg(cp + o10);
        float v11 = __ldg(cp + o11);
        float top = v00 * (1.0f - wx) + v01 * wx;
        float bot = v10 * (1.0f - wx) + v11 * wx;
        d0 = top * (1.0f - wy) + bot * wy;
    }
    // channel 1
    {
        const float* cp1 = cp + CP_ * CP_;
        float v00 = __ldg(cp1 + o00);
        float v01 = __ldg(cp1 + o01);
        float v10 = __ldg(cp1 + o10);
        float v11 = __ldg(cp1 + o11);
        float top = v00 * (1.0f - wx) + v01 * wx;
        float bot = v10 * (1.0f - wx) + v11 * wx;
        d1 = top * (1.0f - wy) + bot * wy;
    }
}

// ---------------------------------------------------------------------------
// Fused kernel: one thread per (h, w) pixel. Computes the deformation + sample
// coordinates ONCE, writes the def-field output, then loops over all 16 batches
// x 3 channels doing only the 4-tap bilinear gather + store.
// Grid: (W/256, H). Block: 256.
// ---------------------------------------------------------------------------
__global__ __launch_bounds__(256)
void bspline_fused_kernel(const float* __restrict__ x,
                          const float* __restrict__ cp,
                          float* __restrict__ out,
                          float* __restrict__ def_out)
{
    int w = blockIdx.x * blockDim.x + threadIdx.x;
    int h = blockIdx.y;

    float gx = -1.0f + (float)w * STEP_;
    float gy = -1.0f + (float)h * STEP_;

    float d0, d1;
    sample_deformation(cp, gx, gy, d0, d1);   // cp is 9.8KB -> L1 resident

    int pix = h * W_ + w;
    def_out[pix]       = d0;   // deformation_field[0]
    def_out[HW_ + pix] = d1;   // deformation_field[1]

    // samp = (gx + def[1], gy + def[0])
    float sx = gx + d1;
    float sy = gy + d0;

    float ix = (sx + 1.0f) * 0.5f * 1023.0f;
    float iy = (sy + 1.0f) * 0.5f * 1023.0f;
    ix = fminf(fmaxf(ix, 0.0f), 1023.0f);
    iy = fminf(fmaxf(iy, 0.0f), 1023.0f);
    float ix0f = floorf(ix);
    float iy0f = floorf(iy);
    float wx = ix - ix0f;
    float wy = iy - iy0f;
    int ix0 = (int)ix0f;
    int iy0 = (int)iy0f;
    int ix1 = min(ix0 + 1, W_ - 1);
    int iy1 = min(iy0 + 1, H_ - 1);

    float omwx = 1.0f - wx;
    float omwy = 1.0f - wy;

    // Four tap offsets within one channel plane (computed once).
    int r0 = iy0 * W_;
    int r1 = iy1 * W_;
    int o00 = r0 + ix0;
    int o01 = r0 + ix1;
    int o10 = r1 + ix0;
    int o11 = r1 + ix1;

    // Batch x channel gather loop: only loads/lerps/stores inside.
#pragma unroll 4
    for (int b = 0; b < B_; b++) {
        const float* xb = x + (size_t)b * CHW_;
        size_t ob = (size_t)b * CHW_ + (size_t)pix;
#pragma unroll
        for (int c = 0; c < C_; c++) {
            const float* xc = xb + (size_t)c * HW_;
            float v00 = __ldg(xc + o00);
            float v01 = __ldg(xc + o01);
            float v10 = __ldg(xc + o10);
            float v11 = __ldg(xc + o11);
            float top = v00 * omwx + v01 * wx;
            float bot = v10 * omwx + v11 * wx;
            out[ob + (size_t)c * HW_] = top * omwy + bot * wy;
        }
    }
}

// ---------------------------------------------------------------------------
extern "C" void kernel_launch(void* const* d_in, const int* in_sizes, int n_in,
                              void* d_out, int out_size)
{
    const float* x  = (const float*)d_in[0];  // (16,3,1024,1024) f32
    const float* cp = (const float*)d_in[1];  // (1,2,35,35) f32
    float* out = (float*)d_out;               // transformed(192MB) ++ def(8MB)

    float* def_out = out + (size_t)B_ * CHW_;

    dim3 blk(256, 1, 1);
    dim3 grd(W_ / 256, H_, 1);
    bspline_fused_kernel<<<grd, blk>>>(x, cp, out, def_out);
}